// round 1
// baseline (speedup 1.0000x reference)
#include <cuda_runtime.h>
#include <math.h>

// Problem constants
#define BATCH 4
#define SEQ   2048
#define CDIM  1024
#define NH    16
#define HD    64
#define ROWS  (BATCH*SEQ)      // 8192
#define QKVC  (3*CDIM)         // 3072

// Scratch (allocation-free rule: __device__ globals)
__device__ float g_qkv[(size_t)ROWS * QKVC];  // [B*T, 3C]  q|k|v
__device__ float g_y[(size_t)ROWS * CDIM];    // attention output [B,T,C]

// ---------------------------------------------------------------------------
// SGEMM + bias: C[M,N] = A[M,K] @ B[K,N] + bias[N]
// Tiles: BM=128, BN=64, BK=16. 256 threads, each computes 8x4.
// Requires M%128==0, N%64==0, K%16==0 (true for all three GEMMs here).
// ---------------------------------------------------------------------------
__global__ __launch_bounds__(256)
void sgemm_bias(const float* __restrict__ A, const float* __restrict__ B,
                const float* __restrict__ bias, float* __restrict__ C,
                int M, int N, int K)
{
    __shared__ float As[16 * 128];   // [kk][row]  (A transposed in smem)
    __shared__ float Bs[16 * 64];    // [kk][col]

    const int tid = threadIdx.x;
    const int tx  = tid & 15;        // 0..15  -> 4 cols strided by 16
    const int ty  = tid >> 4;        // 0..15  -> 8 rows strided by 16
    const int rowBase = blockIdx.y * 128;
    const int colBase = blockIdx.x * 64;

    const int bRow = tid >> 4;       // 0..15
    const int bN4  = tid & 15;       // 0..15

    float acc[8][4];
#pragma unroll
    for (int i = 0; i < 8; i++)
#pragma unroll
        for (int j = 0; j < 4; j++) acc[i][j] = 0.f;

    for (int k0 = 0; k0 < K; k0 += 16) {
        __syncthreads();
        // Load A tile [128 rows][16 k] as float4, store transposed
#pragma unroll
        for (int t = 0; t < 2; t++) {
            int fid = tid + t * 256;         // 0..511
            int row = fid >> 2;              // 0..127
            int c4  = fid & 3;               // which 4-float chunk of the 16 k's
            float4 v = *(const float4*)&A[(size_t)(rowBase + row) * K + k0 + c4 * 4];
            As[(c4 * 4 + 0) * 128 + row] = v.x;
            As[(c4 * 4 + 1) * 128 + row] = v.y;
            As[(c4 * 4 + 2) * 128 + row] = v.z;
            As[(c4 * 4 + 3) * 128 + row] = v.w;
        }
        // Load B tile [16 k][64 n]
        {
            float4 v = *(const float4*)&B[(size_t)(k0 + bRow) * N + colBase + bN4 * 4];
            *(float4*)&Bs[bRow * 64 + bN4 * 4] = v;
        }
        __syncthreads();

#pragma unroll
        for (int kk = 0; kk < 16; kk++) {
            float a[8], bb[4];
#pragma unroll
            for (int i = 0; i < 8; i++) a[i] = As[kk * 128 + ty + i * 16];
#pragma unroll
            for (int j = 0; j < 4; j++) bb[j] = Bs[kk * 64 + tx + j * 16];
#pragma unroll
            for (int i = 0; i < 8; i++)
#pragma unroll
                for (int j = 0; j < 4; j++) acc[i][j] += a[i] * bb[j];
        }
    }

#pragma unroll
    for (int i = 0; i < 8; i++) {
        int row = rowBase + ty + i * 16;
#pragma unroll
        for (int j = 0; j < 4; j++) {
            int col = colBase + tx + j * 16;
            C[(size_t)row * N + col] = acc[i][j] + bias[col];
        }
    }
}

// ---------------------------------------------------------------------------
// Flash-style causal attention, fp32.
// Grid: (T/64, H, B). Block: 256 threads.
// BQ=64 queries/block, BKV=32 keys per inner tile, HD=64.
// Thread map: tx = tid&7 -> 4 score-cols (tx*4..+3); ty = tid>>3 -> 2 rows.
// O dims owned per thread: d = tx + 8*k, k=0..7 (conflict-free Vs reads).
// ---------------------------------------------------------------------------
__global__ __launch_bounds__(256)
void attn_kernel(const float* __restrict__ qkv, float* __restrict__ y)
{
    const int qt = blockIdx.x;           // 0..31
    const int h  = blockIdx.y;           // 0..15
    const int b  = blockIdx.z;           // 0..3
    const int q0 = qt * 64;

    const int tid = threadIdx.x;
    const int tx  = tid & 7;             // 0..7
    const int ty  = tid >> 3;            // 0..31
    const int r0  = ty * 2;              // 2 rows
    const int c0  = tx * 4;              // 4 cols

    __shared__ float Qs[64 * 65];
    __shared__ float Ks[32 * 65];
    __shared__ float Vs[32 * 64];
    __shared__ float Ps[64 * 33];

    const size_t base = (size_t)b * SEQ * QKVC;
    const int hoff = h * HD;

    // Load Q tile, pre-scaled by 1/sqrt(HD) = 0.125
    for (int idx = tid; idx < 64 * 64; idx += 256) {
        int i = idx >> 6, d = idx & 63;
        Qs[i * 65 + d] = qkv[base + (size_t)(q0 + i) * QKVC + hoff + d] * 0.125f;
    }

    float O[2][8];
    float m[2], l[2];
#pragma unroll
    for (int r = 0; r < 2; r++) {
        m[r] = -INFINITY; l[r] = 0.f;
#pragma unroll
        for (int k = 0; k < 8; k++) O[r][k] = 0.f;
    }

    const int ntiles = (q0 + 64) >> 5;   // causal: only kv tiles with k0 <= q0+63
    for (int kt = 0; kt < ntiles; kt++) {
        const int k0 = kt << 5;
        __syncthreads();
        // Load K,V tiles (32x64 each)
        for (int idx = tid; idx < 32 * 64; idx += 256) {
            int j = idx >> 6, d = idx & 63;
            size_t g = base + (size_t)(k0 + j) * QKVC + hoff + d;
            Ks[j * 65 + d] = qkv[g + CDIM];
            Vs[j * 64 + d] = qkv[g + 2 * CDIM];
        }
        __syncthreads();

        // S = Q K^T (pre-scaled)
        float s[2][4];
#pragma unroll
        for (int r = 0; r < 2; r++)
#pragma unroll
            for (int c = 0; c < 4; c++) s[r][c] = 0.f;

        for (int d = 0; d < 64; d++) {
            float qa = Qs[(r0 + 0) * 65 + d];
            float qb = Qs[(r0 + 1) * 65 + d];
#pragma unroll
            for (int c = 0; c < 4; c++) {
                float kv = Ks[(c0 + c) * 65 + d];
                s[0][c] += qa * kv;
                s[1][c] += qb * kv;
            }
        }

        // causal mask
#pragma unroll
        for (int r = 0; r < 2; r++) {
            int qi = q0 + r0 + r;
#pragma unroll
            for (int c = 0; c < 4; c++)
                if (k0 + c0 + c > qi) s[r][c] = -INFINITY;
        }

        // online softmax update
#pragma unroll
        for (int r = 0; r < 2; r++) {
            float mt = fmaxf(fmaxf(s[r][0], s[r][1]), fmaxf(s[r][2], s[r][3]));
#pragma unroll
            for (int off = 1; off < 8; off <<= 1)
                mt = fmaxf(mt, __shfl_xor_sync(0xffffffffu, mt, off));
            float mn = fmaxf(m[r], mt);
            float alpha = __expf(m[r] - mn);
            m[r] = mn;
            float ls = 0.f;
#pragma unroll
            for (int c = 0; c < 4; c++) {
                float p = __expf(s[r][c] - mn);
                ls += p;
                Ps[(r0 + r) * 33 + c0 + c] = p;
            }
#pragma unroll
            for (int off = 1; off < 8; off <<= 1)
                ls += __shfl_xor_sync(0xffffffffu, ls, off);
            l[r] = l[r] * alpha + ls;
#pragma unroll
            for (int k = 0; k < 8; k++) O[r][k] *= alpha;
        }
        __syncthreads();

        // O += P @ V
        for (int j = 0; j < 32; j++) {
            float p0 = Ps[(r0 + 0) * 33 + j];
            float p1 = Ps[(r0 + 1) * 33 + j];
#pragma unroll
            for (int k = 0; k < 8; k++) {
                float v = Vs[j * 64 + tx + 8 * k];
                O[0][k] += p0 * v;
                O[1][k] += p1 * v;
            }
        }
    }

    // normalize + write y[b, q, h*64 + d]
#pragma unroll
    for (int r = 0; r < 2; r++) {
        float inv = 1.f / l[r];
        size_t rowoff = ((size_t)b * SEQ + q0 + r0 + r) * CDIM + hoff;
#pragma unroll
        for (int k = 0; k < 8; k++)
            y[rowoff + tx + 8 * k] = O[r][k] * inv;
    }
}

// ---------------------------------------------------------------------------
extern "C" void kernel_launch(void* const* d_in, const int* in_sizes, int n_in,
                              void* d_out, int out_size)
{
    const float* x      = (const float*)d_in[0];
    const float* W_attn = (const float*)d_in[1];
    const float* b_attn = (const float*)d_in[2];
    const float* W_proj = (const float*)d_in[3];
    const float* b_proj = (const float*)d_in[4];
    float* out = (float*)d_out;

    float *qkv, *y;
    cudaGetSymbolAddress((void**)&qkv, g_qkv);
    cudaGetSymbolAddress((void**)&y,   g_y);

    // 1) qkv = x @ W_attn + b_attn          [8192,3072]
    sgemm_bias<<<dim3(QKVC / 64, ROWS / 128), 256>>>(x, W_attn, b_attn, qkv,
                                                     ROWS, QKVC, CDIM);
    // 2) attention -> y                     [8192,1024]
    attn_kernel<<<dim3(SEQ / 64, NH, BATCH), 256>>>(qkv, y);
    // 3) out = y @ W_proj + b_proj          [8192,1024]
    sgemm_bias<<<dim3(CDIM / 64, ROWS / 128), 256>>>(y, W_proj, b_proj, out,
                                                     ROWS, CDIM, CDIM);
}

// round 2
// speedup vs baseline: 1.7246x; 1.7246x over previous
#include <cuda_runtime.h>
#include <math.h>

// Problem constants
#define BATCH 4
#define SEQ   2048
#define CDIM  1024
#define NH    16
#define HD    64
#define ROWS  (BATCH*SEQ)      // 8192
#define QKVC  (3*CDIM)         // 3072

// Scratch (allocation-free rule: __device__ globals)
__device__ float g_qkv[(size_t)ROWS * QKVC];  // [B*T, 3C]  q|k|v
__device__ float g_y[(size_t)ROWS * CDIM];    // attention output [B,T,C]

// ---------------------------------------------------------------------------
// tf32 tensor-core GEMM + bias: C[M,N] = A[M,K] @ B[K,N] + bias[N]
// Block tile 128x128x16, 256 threads = 8 warps (2 x 4), warp tile 64x32.
// mma.sync.m16n8k8.tf32, cp.async double-buffered smem.
// Requires M%128==0, N%128==0, K%16==0.
// ---------------------------------------------------------------------------
#define AS_STRIDE 20    // 16 + 4 pad: conflict-free A fragment loads
#define BS_STRIDE 136   // 128 + 8 pad: conflict-free B fragment loads

__device__ __forceinline__ unsigned f2tf32(float f) {
    unsigned r;
    asm("cvt.rna.tf32.f32 %0, %1;" : "=r"(r) : "f"(f));
    return r;
}

__device__ __forceinline__ void mma_tf32(float c[4], unsigned a0, unsigned a1,
                                         unsigned a2, unsigned a3,
                                         unsigned b0, unsigned b1) {
    asm volatile(
        "mma.sync.aligned.m16n8k8.row.col.f32.tf32.tf32.f32 "
        "{%0,%1,%2,%3}, {%4,%5,%6,%7}, {%8,%9}, {%0,%1,%2,%3};\n"
        : "+f"(c[0]), "+f"(c[1]), "+f"(c[2]), "+f"(c[3])
        : "r"(a0), "r"(a1), "r"(a2), "r"(a3), "r"(b0), "r"(b1));
}

__device__ __forceinline__ void cp16(unsigned smem_addr, const void* gptr) {
    asm volatile("cp.async.cg.shared.global [%0], [%1], 16;\n"
                 :: "r"(smem_addr), "l"(gptr));
}

__global__ __launch_bounds__(256)
void gemm_tf32(const float* __restrict__ A, const float* __restrict__ B,
               const float* __restrict__ bias, float* __restrict__ C,
               int M, int N, int K)
{
    __shared__ float As[2][128 * AS_STRIDE];
    __shared__ float Bs[2][16 * BS_STRIDE];

    const int tid   = threadIdx.x;
    const int wid   = tid >> 5;
    const int lane  = tid & 31;
    const int warpM = wid >> 2;          // 0..1
    const int warpN = wid & 3;           // 0..3
    const int group = lane >> 2;         // 0..7
    const int tig   = lane & 3;          // 0..3

    const int rowBase = blockIdx.y * 128;
    const int colBase = blockIdx.x * 128;

    // load index precompute
    const int aRow = tid >> 2;           // 0..63 (+64 for second chunk)
    const int aC4  = tid & 3;            // 4 float4 per 16-col row
    const int bRow = tid >> 5;           // 0..7 (+8)
    const int bC4  = tid & 31;           // 32 float4 per 128-col row

    const unsigned sAs0 = (unsigned)__cvta_generic_to_shared(&As[0][0]);
    const unsigned sAs1 = (unsigned)__cvta_generic_to_shared(&As[1][0]);
    const unsigned sBs0 = (unsigned)__cvta_generic_to_shared(&Bs[0][0]);
    const unsigned sBs1 = (unsigned)__cvta_generic_to_shared(&Bs[1][0]);

    float acc[4][4][4];
#pragma unroll
    for (int mt = 0; mt < 4; mt++)
#pragma unroll
        for (int nt = 0; nt < 4; nt++)
#pragma unroll
            for (int i = 0; i < 4; i++) acc[mt][nt][i] = 0.f;

    const int nTiles = K >> 4;

    // ---- tile load macro-ish lambdas ----
    auto loadTile = [&](int s, int k0) {
        unsigned sA = s ? sAs1 : sAs0;
        unsigned sB = s ? sBs1 : sBs0;
#pragma unroll
        for (int i = 0; i < 2; i++) {
            int row = aRow + i * 64;
            cp16(sA + (row * AS_STRIDE + aC4 * 4) * 4,
                 A + (size_t)(rowBase + row) * K + k0 + aC4 * 4);
        }
#pragma unroll
        for (int i = 0; i < 2; i++) {
            int row = bRow + i * 8;
            cp16(sB + (row * BS_STRIDE + bC4 * 4) * 4,
                 B + (size_t)(k0 + row) * N + colBase + bC4 * 4);
        }
    };

    // prologue
    loadTile(0, 0);
    asm volatile("cp.async.commit_group;\n" ::);

    for (int kt = 0; kt < nTiles; kt++) {
        asm volatile("cp.async.wait_group 0;\n" ::);
        __syncthreads();

        int nxt = kt + 1;
        if (nxt < nTiles) loadTile(nxt & 1, nxt << 4);
        asm volatile("cp.async.commit_group;\n" ::);

        const float* as = As[kt & 1];
        const float* bs = Bs[kt & 1];

#pragma unroll
        for (int ks = 0; ks < 2; ks++) {
            const int kb = ks * 8;
            unsigned af[4][4];
#pragma unroll
            for (int mt = 0; mt < 4; mt++) {
                int r = warpM * 64 + mt * 16 + group;
                af[mt][0] = f2tf32(as[(r + 0) * AS_STRIDE + kb + tig]);
                af[mt][1] = f2tf32(as[(r + 8) * AS_STRIDE + kb + tig]);
                af[mt][2] = f2tf32(as[(r + 0) * AS_STRIDE + kb + tig + 4]);
                af[mt][3] = f2tf32(as[(r + 8) * AS_STRIDE + kb + tig + 4]);
            }
            unsigned bf[4][2];
#pragma unroll
            for (int nt = 0; nt < 4; nt++) {
                int c = warpN * 32 + nt * 8 + group;
                bf[nt][0] = f2tf32(bs[(kb + tig + 0) * BS_STRIDE + c]);
                bf[nt][1] = f2tf32(bs[(kb + tig + 4) * BS_STRIDE + c]);
            }
#pragma unroll
            for (int mt = 0; mt < 4; mt++)
#pragma unroll
                for (int nt = 0; nt < 4; nt++)
                    mma_tf32(acc[mt][nt], af[mt][0], af[mt][1], af[mt][2],
                             af[mt][3], bf[nt][0], bf[nt][1]);
        }
        __syncthreads();
    }

    // epilogue: C = acc + bias, float2 stores
#pragma unroll
    for (int mt = 0; mt < 4; mt++) {
        int r0 = rowBase + warpM * 64 + mt * 16 + group;
#pragma unroll
        for (int nt = 0; nt < 4; nt++) {
            int c = colBase + warpN * 32 + nt * 8 + 2 * tig;
            float b0 = bias[c], b1 = bias[c + 1];
            float2 v0 = make_float2(acc[mt][nt][0] + b0, acc[mt][nt][1] + b1);
            float2 v1 = make_float2(acc[mt][nt][2] + b0, acc[mt][nt][3] + b1);
            *(float2*)&C[(size_t)(r0 + 0) * N + c] = v0;
            *(float2*)&C[(size_t)(r0 + 8) * N + c] = v1;
        }
    }
}

// ---------------------------------------------------------------------------
// Flash-style causal attention, fp32 (unchanged from R0; tensor-core next).
// ---------------------------------------------------------------------------
__global__ __launch_bounds__(256)
void attn_kernel(const float* __restrict__ qkv, float* __restrict__ y)
{
    const int qt = blockIdx.x;
    const int h  = blockIdx.y;
    const int b  = blockIdx.z;
    const int q0 = qt * 64;

    const int tid = threadIdx.x;
    const int tx  = tid & 7;
    const int ty  = tid >> 3;
    const int r0  = ty * 2;
    const int c0  = tx * 4;

    __shared__ float Qs[64 * 65];
    __shared__ float Ks[32 * 65];
    __shared__ float Vs[32 * 64];
    __shared__ float Ps[64 * 33];

    const size_t base = (size_t)b * SEQ * QKVC;
    const int hoff = h * HD;

    for (int idx = tid; idx < 64 * 64; idx += 256) {
        int i = idx >> 6, d = idx & 63;
        Qs[i * 65 + d] = qkv[base + (size_t)(q0 + i) * QKVC + hoff + d] * 0.125f;
    }

    float O[2][8];
    float m[2], l[2];
#pragma unroll
    for (int r = 0; r < 2; r++) {
        m[r] = -INFINITY; l[r] = 0.f;
#pragma unroll
        for (int k = 0; k < 8; k++) O[r][k] = 0.f;
    }

    const int ntiles = (q0 + 64) >> 5;
    for (int kt = 0; kt < ntiles; kt++) {
        const int k0 = kt << 5;
        __syncthreads();
        for (int idx = tid; idx < 32 * 64; idx += 256) {
            int j = idx >> 6, d = idx & 63;
            size_t g = base + (size_t)(k0 + j) * QKVC + hoff + d;
            Ks[j * 65 + d] = qkv[g + CDIM];
            Vs[j * 64 + d] = qkv[g + 2 * CDIM];
        }
        __syncthreads();

        float s[2][4];
#pragma unroll
        for (int r = 0; r < 2; r++)
#pragma unroll
            for (int c = 0; c < 4; c++) s[r][c] = 0.f;

        for (int d = 0; d < 64; d++) {
            float qa = Qs[(r0 + 0) * 65 + d];
            float qb = Qs[(r0 + 1) * 65 + d];
#pragma unroll
            for (int c = 0; c < 4; c++) {
                float kv = Ks[(c0 + c) * 65 + d];
                s[0][c] += qa * kv;
                s[1][c] += qb * kv;
            }
        }

#pragma unroll
        for (int r = 0; r < 2; r++) {
            int qi = q0 + r0 + r;
#pragma unroll
            for (int c = 0; c < 4; c++)
                if (k0 + c0 + c > qi) s[r][c] = -INFINITY;
        }

#pragma unroll
        for (int r = 0; r < 2; r++) {
            float mt = fmaxf(fmaxf(s[r][0], s[r][1]), fmaxf(s[r][2], s[r][3]));
#pragma unroll
            for (int off = 1; off < 8; off <<= 1)
                mt = fmaxf(mt, __shfl_xor_sync(0xffffffffu, mt, off));
            float mn = fmaxf(m[r], mt);
            float alpha = __expf(m[r] - mn);
            m[r] = mn;
            float ls = 0.f;
#pragma unroll
            for (int c = 0; c < 4; c++) {
                float p = __expf(s[r][c] - mn);
                ls += p;
                Ps[(r0 + r) * 33 + c0 + c] = p;
            }
#pragma unroll
            for (int off = 1; off < 8; off <<= 1)
                ls += __shfl_xor_sync(0xffffffffu, ls, off);
            l[r] = l[r] * alpha + ls;
#pragma unroll
            for (int k = 0; k < 8; k++) O[r][k] *= alpha;
        }
        __syncthreads();

        for (int j = 0; j < 32; j++) {
            float p0 = Ps[(r0 + 0) * 33 + j];
            float p1 = Ps[(r0 + 1) * 33 + j];
#pragma unroll
            for (int k = 0; k < 8; k++) {
                float v = Vs[j * 64 + tx + 8 * k];
                O[0][k] += p0 * v;
                O[1][k] += p1 * v;
            }
        }
    }

#pragma unroll
    for (int r = 0; r < 2; r++) {
        float inv = 1.f / l[r];
        size_t rowoff = ((size_t)b * SEQ + q0 + r0 + r) * CDIM + hoff;
#pragma unroll
        for (int k = 0; k < 8; k++)
            y[rowoff + tx + 8 * k] = O[r][k] * inv;
    }
}

// ---------------------------------------------------------------------------
extern "C" void kernel_launch(void* const* d_in, const int* in_sizes, int n_in,
                              void* d_out, int out_size)
{
    const float* x      = (const float*)d_in[0];
    const float* W_attn = (const float*)d_in[1];
    const float* b_attn = (const float*)d_in[2];
    const float* W_proj = (const float*)d_in[3];
    const float* b_proj = (const float*)d_in[4];
    float* out = (float*)d_out;

    float *qkv, *y;
    cudaGetSymbolAddress((void**)&qkv, g_qkv);
    cudaGetSymbolAddress((void**)&y,   g_y);

    // 1) qkv = x @ W_attn + b_attn          [8192,3072]
    gemm_tf32<<<dim3(QKVC / 128, ROWS / 128), 256>>>(x, W_attn, b_attn, qkv,
                                                     ROWS, QKVC, CDIM);
    // 2) attention -> y                     [8192,1024]
    attn_kernel<<<dim3(SEQ / 64, NH, BATCH), 256>>>(qkv, y);
    // 3) out = y @ W_proj + b_proj          [8192,1024]
    gemm_tf32<<<dim3(CDIM / 128, ROWS / 128), 256>>>(y, W_proj, b_proj, out,
                                                     ROWS, CDIM, CDIM);
}

// round 3
// speedup vs baseline: 4.4178x; 2.5616x over previous
#include <cuda_runtime.h>
#include <math.h>

// Problem constants
#define BATCH 4
#define SEQ   2048
#define CDIM  1024
#define NH    16
#define HD    64
#define ROWS  (BATCH*SEQ)      // 8192
#define QKVC  (3*CDIM)         // 3072

// Scratch (allocation-free rule: __device__ globals)
__device__ float g_qkv[(size_t)ROWS * QKVC];  // [B*T, 3C]  q|k|v
__device__ float g_y[(size_t)ROWS * CDIM];    // attention output [B,T,C]

__device__ __forceinline__ unsigned f2tf32(float f) {
    unsigned r;
    asm("cvt.rna.tf32.f32 %0, %1;" : "=r"(r) : "f"(f));
    return r;
}

__device__ __forceinline__ void mma_tf32(float c[4], unsigned a0, unsigned a1,
                                         unsigned a2, unsigned a3,
                                         unsigned b0, unsigned b1) {
    asm volatile(
        "mma.sync.aligned.m16n8k8.row.col.f32.tf32.tf32.f32 "
        "{%0,%1,%2,%3}, {%4,%5,%6,%7}, {%8,%9}, {%0,%1,%2,%3};\n"
        : "+f"(c[0]), "+f"(c[1]), "+f"(c[2]), "+f"(c[3])
        : "r"(a0), "r"(a1), "r"(a2), "r"(a3), "r"(b0), "r"(b1));
}

__device__ __forceinline__ void cp16(unsigned smem_addr, const void* gptr) {
    asm volatile("cp.async.cg.shared.global [%0], [%1], 16;\n"
                 :: "r"(smem_addr), "l"(gptr));
}

// ---------------------------------------------------------------------------
// tf32 tensor-core GEMM + bias (unchanged from R1)
// ---------------------------------------------------------------------------
#define AS_STRIDE 20
#define BS_STRIDE 136

__global__ __launch_bounds__(256)
void gemm_tf32(const float* __restrict__ A, const float* __restrict__ B,
               const float* __restrict__ bias, float* __restrict__ C,
               int M, int N, int K)
{
    __shared__ float As[2][128 * AS_STRIDE];
    __shared__ float Bs[2][16 * BS_STRIDE];

    const int tid   = threadIdx.x;
    const int wid   = tid >> 5;
    const int lane  = tid & 31;
    const int warpM = wid >> 2;
    const int warpN = wid & 3;
    const int group = lane >> 2;
    const int tig   = lane & 3;

    const int rowBase = blockIdx.y * 128;
    const int colBase = blockIdx.x * 128;

    const int aRow = tid >> 2;
    const int aC4  = tid & 3;
    const int bRow = tid >> 5;
    const int bC4  = tid & 31;

    const unsigned sAs0 = (unsigned)__cvta_generic_to_shared(&As[0][0]);
    const unsigned sAs1 = (unsigned)__cvta_generic_to_shared(&As[1][0]);
    const unsigned sBs0 = (unsigned)__cvta_generic_to_shared(&Bs[0][0]);
    const unsigned sBs1 = (unsigned)__cvta_generic_to_shared(&Bs[1][0]);

    float acc[4][4][4];
#pragma unroll
    for (int mt = 0; mt < 4; mt++)
#pragma unroll
        for (int nt = 0; nt < 4; nt++)
#pragma unroll
            for (int i = 0; i < 4; i++) acc[mt][nt][i] = 0.f;

    const int nTiles = K >> 4;

    auto loadTile = [&](int s, int k0) {
        unsigned sA = s ? sAs1 : sAs0;
        unsigned sB = s ? sBs1 : sBs0;
#pragma unroll
        for (int i = 0; i < 2; i++) {
            int row = aRow + i * 64;
            cp16(sA + (row * AS_STRIDE + aC4 * 4) * 4,
                 A + (size_t)(rowBase + row) * K + k0 + aC4 * 4);
        }
#pragma unroll
        for (int i = 0; i < 2; i++) {
            int row = bRow + i * 8;
            cp16(sB + (row * BS_STRIDE + bC4 * 4) * 4,
                 B + (size_t)(k0 + row) * N + colBase + bC4 * 4);
        }
    };

    loadTile(0, 0);
    asm volatile("cp.async.commit_group;\n" ::);

    for (int kt = 0; kt < nTiles; kt++) {
        asm volatile("cp.async.wait_group 0;\n" ::);
        __syncthreads();

        int nxt = kt + 1;
        if (nxt < nTiles) loadTile(nxt & 1, nxt << 4);
        asm volatile("cp.async.commit_group;\n" ::);

        const float* as = As[kt & 1];
        const float* bs = Bs[kt & 1];

#pragma unroll
        for (int ks = 0; ks < 2; ks++) {
            const int kb = ks * 8;
            unsigned af[4][4];
#pragma unroll
            for (int mt = 0; mt < 4; mt++) {
                int r = warpM * 64 + mt * 16 + group;
                af[mt][0] = f2tf32(as[(r + 0) * AS_STRIDE + kb + tig]);
                af[mt][1] = f2tf32(as[(r + 8) * AS_STRIDE + kb + tig]);
                af[mt][2] = f2tf32(as[(r + 0) * AS_STRIDE + kb + tig + 4]);
                af[mt][3] = f2tf32(as[(r + 8) * AS_STRIDE + kb + tig + 4]);
            }
            unsigned bf[4][2];
#pragma unroll
            for (int nt = 0; nt < 4; nt++) {
                int c = warpN * 32 + nt * 8 + group;
                bf[nt][0] = f2tf32(bs[(kb + tig + 0) * BS_STRIDE + c]);
                bf[nt][1] = f2tf32(bs[(kb + tig + 4) * BS_STRIDE + c]);
            }
#pragma unroll
            for (int mt = 0; mt < 4; mt++)
#pragma unroll
                for (int nt = 0; nt < 4; nt++)
                    mma_tf32(acc[mt][nt], af[mt][0], af[mt][1], af[mt][2],
                             af[mt][3], bf[nt][0], bf[nt][1]);
        }
        __syncthreads();
    }

#pragma unroll
    for (int mt = 0; mt < 4; mt++) {
        int r0 = rowBase + warpM * 64 + mt * 16 + group;
#pragma unroll
        for (int nt = 0; nt < 4; nt++) {
            int c = colBase + warpN * 32 + nt * 8 + 2 * tig;
            float b0 = bias[c], b1 = bias[c + 1];
            float2 v0 = make_float2(acc[mt][nt][0] + b0, acc[mt][nt][1] + b1);
            float2 v1 = make_float2(acc[mt][nt][2] + b0, acc[mt][nt][3] + b1);
            *(float2*)&C[(size_t)(r0 + 0) * N + c] = v0;
            *(float2*)&C[(size_t)(r0 + 8) * N + c] = v1;
        }
    }
}

// ---------------------------------------------------------------------------
// Tensor-core flash attention, tf32 mma for S=QK^T and O=PV.
// Grid: (T/128, H, B). Block: 256 threads = 8 warps; warp w owns q rows
// [q0+16w, q0+16w+16). BKV=64 keys per tile.
// Smem strides chosen for conflict-free mma fragment LDS:
//   Ks/Ps stride 68 -> bank = (4*group + tig) % 32 (bijective)
//   Vs stride 72    -> bank = (8*tig + group) % 32 (bijective)
// ---------------------------------------------------------------------------
#define BQ 128
#define BKV 64
#define KS_STRIDE 68
#define VS_STRIDE 72
#define PS_STRIDE 68
#define ATTN_SMEM ((BKV*KS_STRIDE + BKV*VS_STRIDE + BQ*PS_STRIDE) * 4)

__global__ __launch_bounds__(256)
void attn_tc(const float* __restrict__ qkv, float* __restrict__ y)
{
    extern __shared__ unsigned smem[];
    unsigned* Ks = smem;                       // [BKV][KS_STRIDE]
    unsigned* Vs = Ks + BKV * KS_STRIDE;       // [BKV][VS_STRIDE]
    unsigned* Ps = Vs + BKV * VS_STRIDE;       // [BQ][PS_STRIDE]

    const int q0 = blockIdx.x * BQ;
    const int h  = blockIdx.y;
    const int b  = blockIdx.z;

    const int tid  = threadIdx.x;
    const int w    = tid >> 5;
    const int lane = tid & 31;
    const int g    = lane >> 2;   // group 0..7
    const int t    = lane & 3;    // tig   0..3

    const size_t base = (size_t)b * SEQ * QKVC;
    const int hoff = h * HD;
    const int rowA = q0 + w * 16 + g;          // this thread's upper row

    // Q fragments (loop-invariant): rows rowA, rowA+8; pre-scaled by 1/8
    unsigned qa[8][4];
    {
        const float* Q0 = qkv + base + (size_t)rowA * QKVC + hoff;
        const float* Q8 = Q0 + (size_t)8 * QKVC;
#pragma unroll
        for (int kb = 0; kb < 8; kb++) {
            qa[kb][0] = f2tf32(Q0[kb * 8 + t] * 0.125f);
            qa[kb][1] = f2tf32(Q8[kb * 8 + t] * 0.125f);
            qa[kb][2] = f2tf32(Q0[kb * 8 + t + 4] * 0.125f);
            qa[kb][3] = f2tf32(Q8[kb * 8 + t + 4] * 0.125f);
        }
    }

    float O[8][4];
#pragma unroll
    for (int nt = 0; nt < 8; nt++)
#pragma unroll
        for (int i = 0; i < 4; i++) O[nt][i] = 0.f;
    float m0 = -INFINITY, m1 = -INFINITY, l0 = 0.f, l1 = 0.f;

    const int ntiles = (q0 + BQ) >> 6;
    for (int kt = 0; kt < ntiles; kt++) {
        const int k0 = kt << 6;
        __syncthreads();
        // Cooperative load K,V tiles (64x64 each), convert to tf32 in smem
#pragma unroll
        for (int i = 0; i < 4; i++) {
            int idx = tid + i * 256;           // 0..1023
            int row = idx >> 4, c4 = idx & 15;
            const float* gk = qkv + base + (size_t)(k0 + row) * QKVC + hoff + c4 * 4;
            float4 kv = *(const float4*)(gk + CDIM);
            float4 vv = *(const float4*)(gk + 2 * CDIM);
            uint4 ku = make_uint4(f2tf32(kv.x), f2tf32(kv.y), f2tf32(kv.z), f2tf32(kv.w));
            uint4 vu = make_uint4(f2tf32(vv.x), f2tf32(vv.y), f2tf32(vv.z), f2tf32(vv.w));
            *(uint4*)&Ks[row * KS_STRIDE + c4 * 4] = ku;
            *(uint4*)&Vs[row * VS_STRIDE + c4 * 4] = vu;
        }
        __syncthreads();

        // S = Q @ K^T  (16 x 64 per warp)
        float S[8][4];
#pragma unroll
        for (int nt = 0; nt < 8; nt++)
#pragma unroll
            for (int i = 0; i < 4; i++) S[nt][i] = 0.f;

#pragma unroll
        for (int kb = 0; kb < 8; kb++) {
#pragma unroll
            for (int nt = 0; nt < 8; nt++) {
                const unsigned* kr = &Ks[(nt * 8 + g) * KS_STRIDE + kb * 8 + t];
                mma_tf32(S[nt], qa[kb][0], qa[kb][1], qa[kb][2], qa[kb][3],
                         kr[0], kr[4]);
            }
        }

        // causal mask (only diagonal-overlapping tiles do real work)
        if (k0 + BKV - 1 > q0 + w * 16) {
#pragma unroll
            for (int nt = 0; nt < 8; nt++) {
                int col = k0 + nt * 8 + 2 * t;
                if (col > rowA)     S[nt][0] = -INFINITY;
                if (col + 1 > rowA) S[nt][1] = -INFINITY;
                if (col > rowA + 8)     S[nt][2] = -INFINITY;
                if (col + 1 > rowA + 8) S[nt][3] = -INFINITY;
            }
        }

        // online softmax (rows rowA and rowA+8)
        float mt0 = -INFINITY, mt1 = -INFINITY;
#pragma unroll
        for (int nt = 0; nt < 8; nt++) {
            mt0 = fmaxf(mt0, fmaxf(S[nt][0], S[nt][1]));
            mt1 = fmaxf(mt1, fmaxf(S[nt][2], S[nt][3]));
        }
#pragma unroll
        for (int off = 1; off < 4; off <<= 1) {
            mt0 = fmaxf(mt0, __shfl_xor_sync(0xffffffffu, mt0, off));
            mt1 = fmaxf(mt1, __shfl_xor_sync(0xffffffffu, mt1, off));
        }
        float mn0 = fmaxf(m0, mt0), mn1 = fmaxf(m1, mt1);
        float al0 = __expf(m0 - mn0), al1 = __expf(m1 - mn1);
        m0 = mn0; m1 = mn1;

        float ls0 = 0.f, ls1 = 0.f;
        unsigned* p0 = &Ps[(w * 16 + g) * PS_STRIDE + 2 * t];
        unsigned* p1 = p0 + 8 * PS_STRIDE;
#pragma unroll
        for (int nt = 0; nt < 8; nt++) {
            float e00 = __expf(S[nt][0] - mn0);
            float e01 = __expf(S[nt][1] - mn0);
            float e10 = __expf(S[nt][2] - mn1);
            float e11 = __expf(S[nt][3] - mn1);
            ls0 += e00 + e01;
            ls1 += e10 + e11;
            *(uint2*)&p0[nt * 8] = make_uint2(f2tf32(e00), f2tf32(e01));
            *(uint2*)&p1[nt * 8] = make_uint2(f2tf32(e10), f2tf32(e11));
        }
#pragma unroll
        for (int off = 1; off < 4; off <<= 1) {
            ls0 += __shfl_xor_sync(0xffffffffu, ls0, off);
            ls1 += __shfl_xor_sync(0xffffffffu, ls1, off);
        }
        l0 = l0 * al0 + ls0;
        l1 = l1 * al1 + ls1;
#pragma unroll
        for (int nt = 0; nt < 8; nt++) {
            O[nt][0] *= al0; O[nt][1] *= al0;
            O[nt][2] *= al1; O[nt][3] *= al1;
        }
        __syncwarp();

        // O += P @ V  (A fragments from warp-private Ps region)
        const unsigned* pr0 = &Ps[(w * 16 + g) * PS_STRIDE];
        const unsigned* pr8 = pr0 + 8 * PS_STRIDE;
#pragma unroll
        for (int kb = 0; kb < 8; kb++) {
            unsigned pa0 = pr0[kb * 8 + t];
            unsigned pa1 = pr8[kb * 8 + t];
            unsigned pa2 = pr0[kb * 8 + t + 4];
            unsigned pa3 = pr8[kb * 8 + t + 4];
#pragma unroll
            for (int nt = 0; nt < 8; nt++) {
                const unsigned* vr = &Vs[(kb * 8 + t) * VS_STRIDE + nt * 8 + g];
                mma_tf32(O[nt], pa0, pa1, pa2, pa3, vr[0], vr[4 * VS_STRIDE]);
            }
        }
    }

    // normalize + write
    float inv0 = 1.f / l0, inv1 = 1.f / l1;
    float* y0 = y + ((size_t)b * SEQ + rowA) * CDIM + hoff;
    float* y1 = y0 + (size_t)8 * CDIM;
#pragma unroll
    for (int nt = 0; nt < 8; nt++) {
        *(float2*)&y0[nt * 8 + 2 * t] = make_float2(O[nt][0] * inv0, O[nt][1] * inv0);
        *(float2*)&y1[nt * 8 + 2 * t] = make_float2(O[nt][2] * inv1, O[nt][3] * inv1);
    }
}

// ---------------------------------------------------------------------------
extern "C" void kernel_launch(void* const* d_in, const int* in_sizes, int n_in,
                              void* d_out, int out_size)
{
    const float* x      = (const float*)d_in[0];
    const float* W_attn = (const float*)d_in[1];
    const float* b_attn = (const float*)d_in[2];
    const float* W_proj = (const float*)d_in[3];
    const float* b_proj = (const float*)d_in[4];
    float* out = (float*)d_out;

    float *qkv, *y;
    cudaGetSymbolAddress((void**)&qkv, g_qkv);
    cudaGetSymbolAddress((void**)&y,   g_y);

    cudaFuncSetAttribute(attn_tc, cudaFuncAttributeMaxDynamicSharedMemorySize,
                         ATTN_SMEM);

    // 1) qkv = x @ W_attn + b_attn          [8192,3072]
    gemm_tf32<<<dim3(QKVC / 128, ROWS / 128), 256>>>(x, W_attn, b_attn, qkv,
                                                     ROWS, QKVC, CDIM);
    // 2) attention -> y                     [8192,1024]
    attn_tc<<<dim3(SEQ / BQ, NH, BATCH), 256, ATTN_SMEM>>>(qkv, y);
    // 3) out = y @ W_proj + b_proj          [8192,1024]
    gemm_tf32<<<dim3(CDIM / 128, ROWS / 128), 256>>>(y, W_proj, b_proj, out,
                                                     ROWS, CDIM, CDIM);
}